// round 16
// baseline (speedup 1.0000x reference)
#include <cuda_runtime.h>
#include <cstdint>

#define NN     6144
#define MAXDEG 192
#define FULL   0xffffffffu
#define GRID   768

// ---------------- scratch (device globals; no allocation allowed) -----------
// layer0 row stride 16: [h0..h11, ed0, ed1, es0, es1]
// layer1 row stride 12: [h0..h5, ed0, ed1, pad...]
// layer2 row stride 20: [h0..h15, ed, pad...]
__device__ __align__(16) float g_h0[NN * 16];
__device__ __align__(16) float g_h1[NN * 12];
__device__ __align__(16) float g_h2[NN * 20];
__device__ float g_part[GRID * 16];
__device__ int   g_barc[3];            // zero-initialized
__device__ int   g_barf[3];            // zero-initialized
__device__ int   g_exit;               // zero-initialized

#define XOR_RED(v) { _Pragma("unroll") for (int _o = 16; _o > 0; _o >>= 1) (v) += __shfl_xor_sync(FULL, (v), _o); }

// Grid barrier: arrival = one atomicAdd; wait = plain acquire-loads.
__device__ __forceinline__ void grid_barrier(int id) {
    __syncthreads();
    if (threadIdx.x == 0) {
        __threadfence();
        if (atomicAdd(&g_barc[id], 1) == GRID - 1) {
            g_barc[id] = 0;
            asm volatile("st.global.release.gpu.b32 [%0], %1;"
                         :: "l"(&g_barf[id]), "r"(1) : "memory");
        } else {
            int v;
            do {
                asm volatile("ld.global.acquire.gpu.b32 %0, [%1];"
                             : "=r"(v) : "l"(&g_barf[id]) : "memory");
            } while (v == 0);
        }
    }
    __syncthreads();
}

// Process one 128-column chunk of the adjacency row (ballot compaction).
#define PROCESS_CHUNK(v, cidx) do {                                            \
    unsigned _anyv = (v).x | (v).y | (v).z | (v).w;                            \
    unsigned _any = __ballot_sync(FULL, _anyv != 0);                           \
    if (_any) {                                                                \
        int _col0 = (cidx) * 128 + lane * 4;                                   \
        unsigned _m0 = __ballot_sync(FULL, (v).x != 0);                        \
        unsigned _m1 = __ballot_sync(FULL, (v).y != 0);                        \
        unsigned _m2 = __ballot_sync(FULL, (v).z != 0);                        \
        unsigned _m3 = __ballot_sync(FULL, (v).w != 0);                        \
        int _c0 = __popc(_m0), _c1 = __popc(_m1), _c2 = __popc(_m2);           \
        if ((v).x) { int p = base + __popc(_m0 & lt);                   if (p < MAXDEG) scols[wid][p] = _col0; }     \
        if ((v).y) { int p = base + _c0 + __popc(_m1 & lt);             if (p < MAXDEG) scols[wid][p] = _col0 + 1; } \
        if ((v).z) { int p = base + _c0 + _c1 + __popc(_m2 & lt);       if (p < MAXDEG) scols[wid][p] = _col0 + 2; } \
        if ((v).w) { int p = base + _c0 + _c1 + _c2 + __popc(_m3 & lt); if (p < MAXDEG) scols[wid][p] = _col0 + 3; } \
        base += _c0 + _c1 + _c2 + __popc(_m3);                                 \
    }                                                                          \
} while (0)

// ======================= single fused persistent kernel ======================
__global__ void __launch_bounds__(256, 6) k_gat(
    const float* __restrict__ x,   const float* __restrict__ adj,
    const float* __restrict__ W0,  const float* __restrict__ a0s, const float* __restrict__ a0d,
    const float* __restrict__ W1,  const float* __restrict__ a1s, const float* __restrict__ a1d,
    const float* __restrict__ W2,  const float* __restrict__ a2s, const float* __restrict__ a2d,
    float* __restrict__ out)
{
    __shared__ float sW0[768];
    __shared__ float sa0[24];
    __shared__ float sW1[72];
    __shared__ float sa1[12];
    __shared__ float sW2[96];
    __shared__ float sa2[32];
    __shared__ int   scols[8][MAXDEG];
    __shared__ float shx[8][16];
    __shared__ float shh[8][16];
    __shared__ float sblk[8][16];
    __shared__ __align__(16) uint4 sstage[8][4][32];   // 16 KB cp.async stages

    // ---- load all weights once ----
    for (int i = threadIdx.x; i < 768; i += 256) sW0[i] = W0[i];
    {
        int t = threadIdx.x;
        if (t < 12)  { sa0[t] = a0s[t]; sa0[12 + t] = a0d[t]; }
        if (t >= 32  && t < 104) sW1[t - 32]  = W1[t - 32];
        if (t >= 104 && t < 110) sa1[t - 104] = a1s[t - 104];
        if (t >= 110 && t < 116) sa1[6 + t - 110] = a1d[t - 110];
        if (t >= 128 && t < 224) sW2[t - 128] = W2[t - 128];
        if (t >= 224 && t < 240) sa2[t - 224] = a2d[t - 224];
        if (t >= 240 && t < 256) sa2[16 + t - 240] = a2s[t - 240];
    }
    __syncthreads();

    const int lane = threadIdx.x & 31;
    const int wid  = threadIdx.x >> 5;
    const int node = blockIdx.x * 8 + wid;

    // ============ PHASE 0a: linear0 for own node (es kept in registers) =====
    float es0_0 = 0.f, es1_0 = 0.f;
    {
        float x0 = x[node * 64 + lane];
        float x1 = x[node * 64 + 32 + lane];
        float acc[12];
#pragma unroll
        for (int h = 0; h < 2; h++)
#pragma unroll
            for (int f = 0; f < 6; f++) {
                int hf = h * 6 + f;
                acc[hf] = x0 * sW0[(h * 64 + lane) * 6 + f]
                        + x1 * sW0[(h * 64 + lane + 32) * 6 + f];
            }
#pragma unroll
        for (int i = 0; i < 12; i++) XOR_RED(acc[i]);

        if (lane == 0) {
            float ed0 = 0.f, ed1 = 0.f;
#pragma unroll
            for (int f = 0; f < 6; f++) {
                es0_0 += acc[f]     * sa0[f];       ed0 += acc[f]     * sa0[12 + f];
                es1_0 += acc[6 + f] * sa0[6 + f];   ed1 += acc[6 + f] * sa0[18 + f];
            }
            float4* row = reinterpret_cast<float4*>(&g_h0[node * 16]);
            row[0] = make_float4(acc[0], acc[1], acc[2],  acc[3]);
            row[1] = make_float4(acc[4], acc[5], acc[6],  acc[7]);
            row[2] = make_float4(acc[8], acc[9], acc[10], acc[11]);
            row[3] = make_float4(ed0, ed1, es0_0, es1_0);
        }
        es0_0 = __shfl_sync(FULL, es0_0, 0);
        es1_0 = __shfl_sync(FULL, es1_0, 0);
    }

    grid_barrier(0);   // h0 must be globally visible; scan below is node-private

    // ====== PHASE 0b: scan own adjacency row — cp.async 4-deep pipeline =====
    // 48 chunks of 128 cols (512 B/warp, 16 B/lane). Copy engine keeps 4
    // stages in flight per warp, decoupled from the ballot processing chain.
    int deg;
    {
        int base = 0;
        const unsigned lt = (1u << lane) - 1u;
        const char* arow = reinterpret_cast<const char*>(adj) +
                           (size_t)node * NN * sizeof(float) + lane * 16;
        uint32_t smy = (uint32_t)__cvta_generic_to_shared(&sstage[wid][0][lane]);
        // stage stride in smem = 32 lanes * 16 B = 512 B

        // prologue: fill stages 0..3
#pragma unroll
        for (int s = 0; s < 4; ++s) {
            asm volatile("cp.async.cg.shared.global [%0], [%1], 16;"
                         :: "r"(smy + s * 512), "l"(arow + (size_t)s * 512));
            asm volatile("cp.async.commit_group;");
        }
        // main loop: chunks 0..43, refill chunk c+4 into the freed stage
        for (int c = 0; c < 44; ++c) {
            asm volatile("cp.async.wait_group 3;");
            uint4 v = sstage[wid][c & 3][lane];          // own 16 B -> registers
            asm volatile("cp.async.cg.shared.global [%0], [%1], 16;"
                         :: "r"(smy + ((c + 4) & 3) * 512),
                            "l"(arow + (size_t)(c + 4) * 512));
            asm volatile("cp.async.commit_group;");
            PROCESS_CHUNK(v, c);
        }
        // tail: chunks 44..47
        asm volatile("cp.async.wait_group 0;");
#pragma unroll
        for (int c = 44; c < 48; ++c) {
            uint4 v = sstage[wid][c & 3][lane];
            PROCESS_CHUNK(v, c);
        }
        deg = base < MAXDEG ? base : MAXDEG;
    }
    __syncwarp();

    // ============ PHASE 1: attn layer0 (H=2,F=6) + elu + linear1 ============
    float es0_1 = 0.f, es1_1 = 0.f;
    {
        const int j  = lane >> 2;      // neighbor slot 0..7
        const int fl = lane & 3;       // float4 slot
        const int f0 = fl * 4;

        float4 a = {0.f, 0.f, 0.f, 0.f};
        float ws0 = 0.f, ws1 = 0.f;
#pragma unroll 4
        for (int kb = 0; kb < deg; kb += 8) {
            int k = kb + j;
            bool valid = k < deg;
            int m = scols[wid][valid ? k : deg - 1];
            float4 hv = *reinterpret_cast<const float4*>(&g_h0[m * 16 + f0]);
            float ed0 = __shfl_sync(FULL, hv.x, 3, 4);   // fl=3 holds [ed0,ed1,es0,es1]
            float ed1 = __shfl_sync(FULL, hv.y, 3, 4);
            float e0 = es0_0 + ed0; e0 = e0 > 0.f ? e0 : 0.2f * e0;
            float e1 = es1_0 + ed1; e1 = e1 > 0.f ? e1 : 0.2f * e1;
            float w0 = __expf(e0), w1 = __expf(e1);
            if (valid) {
                ws0 += w0; ws1 += w1;
                float wx = f0     < 6 ? w0 : (f0     < 12 ? w1 : 0.f);
                float wy = f0 + 1 < 6 ? w0 : (f0 + 1 < 12 ? w1 : 0.f);
                float wz = f0 + 2 < 6 ? w0 : (f0 + 2 < 12 ? w1 : 0.f);
                float ww = f0 + 3 < 6 ? w0 : (f0 + 3 < 12 ? w1 : 0.f);
                a.x += wx * hv.x; a.y += wy * hv.y;
                a.z += wz * hv.z; a.w += ww * hv.w;
            }
        }
#pragma unroll
        for (int o = 4; o <= 16; o <<= 1) {
            a.x += __shfl_xor_sync(FULL, a.x, o);
            a.y += __shfl_xor_sync(FULL, a.y, o);
            a.z += __shfl_xor_sync(FULL, a.z, o);
            a.w += __shfl_xor_sync(FULL, a.w, o);
            ws0 += __shfl_xor_sync(FULL, ws0, o);
            ws1 += __shfl_xor_sync(FULL, ws1, o);
        }

        if (lane < 3) {
            float inv0 = 1.f / ws0, inv1 = 1.f / ws1;
            float v0 = a.x * (f0     < 6 ? inv0 : inv1);
            float v1 = a.y * (f0 + 1 < 6 ? inv0 : inv1);
            float v2 = a.z * (f0 + 2 < 6 ? inv0 : inv1);
            float v3 = a.w * (f0 + 3 < 6 ? inv0 : inv1);
            shx[wid][f0]     = v0 > 0.f ? v0 : expm1f(v0);
            shx[wid][f0 + 1] = v1 > 0.f ? v1 : expm1f(v1);
            shx[wid][f0 + 2] = v2 > 0.f ? v2 : expm1f(v2);
            shx[wid][f0 + 3] = v3 > 0.f ? v3 : expm1f(v3);
        }
        __syncwarp();
        if (lane < 6) {
            int h2 = lane / 3, f2 = lane % 3;
            float s = 0.f;
#pragma unroll
            for (int i = 0; i < 12; i++) s += shx[wid][i] * sW1[(h2 * 12 + i) * 3 + f2];
            g_h1[node * 12 + lane] = s;
            shh[wid][lane] = s;
        }
        __syncwarp();
        float es_l = 0.f;
        if (lane < 2) {
            float ed = 0.f;
#pragma unroll
            for (int f2 = 0; f2 < 3; f2++) {
                float hv = shh[wid][lane * 3 + f2];
                es_l += hv * sa1[lane * 3 + f2];
                ed   += hv * sa1[6 + lane * 3 + f2];
            }
            g_h1[node * 12 + 6 + lane] = ed;    // slots 6,7 = ed0,ed1
        }
        es0_1 = __shfl_sync(FULL, es_l, 0);
        es1_1 = __shfl_sync(FULL, es_l, 1);
    }

    grid_barrier(1);

    // ============ PHASE 2: attn layer1 (H=2,F=3) + elu + linear2 ============
    float es_2 = 0.f;
    {
        const int j  = lane >> 1;      // neighbor slot 0..15
        const int fl = lane & 1;

        float4 a = {0.f, 0.f, 0.f, 0.f};
        float ws0 = 0.f, ws1 = 0.f;
#pragma unroll 2
        for (int kb = 0; kb < deg; kb += 16) {
            int k = kb + j;
            bool valid = k < deg;
            int m = scols[wid][valid ? k : deg - 1];
            float4 hv = *reinterpret_cast<const float4*>(&g_h1[m * 12 + fl * 4]);
            float ed0 = __shfl_sync(FULL, hv.z, 1, 2);   // fl=1 holds [f4,f5,ed0,ed1]
            float ed1 = __shfl_sync(FULL, hv.w, 1, 2);
            float e0 = es0_1 + ed0; e0 = e0 > 0.f ? e0 : 0.2f * e0;
            float e1 = es1_1 + ed1; e1 = e1 > 0.f ? e1 : 0.2f * e1;
            float w0 = __expf(e0), w1 = __expf(e1);
            if (valid) {
                ws0 += w0; ws1 += w1;
                if (fl == 0) {            // f0,f1,f2 head0; f3 head1
                    a.x += w0 * hv.x; a.y += w0 * hv.y;
                    a.z += w0 * hv.z; a.w += w1 * hv.w;
                } else {                  // f4,f5 head1
                    a.x += w1 * hv.x; a.y += w1 * hv.y;
                }
            }
        }
#pragma unroll
        for (int o = 2; o <= 16; o <<= 1) {
            a.x += __shfl_xor_sync(FULL, a.x, o);
            a.y += __shfl_xor_sync(FULL, a.y, o);
            a.z += __shfl_xor_sync(FULL, a.z, o);
            a.w += __shfl_xor_sync(FULL, a.w, o);
            ws0 += __shfl_xor_sync(FULL, ws0, o);
            ws1 += __shfl_xor_sync(FULL, ws1, o);
        }

        if (lane < 2) {
            float inv0 = 1.f / ws0, inv1 = 1.f / ws1;
            if (lane == 0) {
                float v0 = a.x * inv0, v1 = a.y * inv0, v2 = a.z * inv0, v3 = a.w * inv1;
                shx[wid][0] = v0 > 0.f ? v0 : expm1f(v0);
                shx[wid][1] = v1 > 0.f ? v1 : expm1f(v1);
                shx[wid][2] = v2 > 0.f ? v2 : expm1f(v2);
                shx[wid][3] = v3 > 0.f ? v3 : expm1f(v3);
            } else {
                float v4 = a.x * inv1, v5 = a.y * inv1;
                shx[wid][4] = v4 > 0.f ? v4 : expm1f(v4);
                shx[wid][5] = v5 > 0.f ? v5 : expm1f(v5);
            }
        }
        __syncwarp();
        if (lane < 16) {
            float s = 0.f;
#pragma unroll
            for (int i = 0; i < 6; i++) s += shx[wid][i] * sW2[i * 16 + lane];
            g_h2[node * 20 + lane] = s;
            shh[wid][lane] = s;
        }
        __syncwarp();
        float d_l = 0.f;
        if (lane < 2) {
#pragma unroll
            for (int f = 0; f < 16; f++) d_l += shh[wid][f] * sa2[lane * 16 + f];
            if (lane == 0) g_h2[node * 20 + 16] = d_l;   // ed (gathered by neighbors)
        }
        es_2 = __shfl_sync(FULL, d_l, 1);                // es stays in registers
    }

    grid_barrier(2);

    // ===== PHASE 3: final attn (H=1,F=16) + relu + deterministic sum ========
    {
        const int j  = lane >> 2;      // neighbor slot 0..7
        const int fl = lane & 3;

        float4 a = {0.f, 0.f, 0.f, 0.f};
        float ws = 0.f;
#pragma unroll 4
        for (int kb = 0; kb < deg; kb += 8) {
            int k = kb + j;
            bool valid = k < deg;
            int m = scols[wid][valid ? k : deg - 1];
            float4 hv = *reinterpret_cast<const float4*>(&g_h2[m * 20 + fl * 4]);
            float ed = g_h2[m * 20 + 16];
            float e = es_2 + ed; e = e > 0.f ? e : 0.2f * e;
            float w = __expf(e);
            if (valid) {
                ws += w;
                a.x += w * hv.x; a.y += w * hv.y;
                a.z += w * hv.z; a.w += w * hv.w;
            }
        }
#pragma unroll
        for (int o = 4; o <= 16; o <<= 1) {
            a.x += __shfl_xor_sync(FULL, a.x, o);
            a.y += __shfl_xor_sync(FULL, a.y, o);
            a.z += __shfl_xor_sync(FULL, a.z, o);
            a.w += __shfl_xor_sync(FULL, a.w, o);
            ws  += __shfl_xor_sync(FULL, ws, o);
        }

        if (lane < 4) {
            float inv = 1.f / ws;
            float v0 = a.x * inv, v1 = a.y * inv, v2 = a.z * inv, v3 = a.w * inv;
            sblk[wid][fl * 4]     = v0 > 0.f ? v0 : 0.f;
            sblk[wid][fl * 4 + 1] = v1 > 0.f ? v1 : 0.f;
            sblk[wid][fl * 4 + 2] = v2 > 0.f ? v2 : 0.f;
            sblk[wid][fl * 4 + 3] = v3 > 0.f ? v3 : 0.f;
        }
    }
    __syncthreads();

    if (threadIdx.x < 16) {
        float p = 0.f;
#pragma unroll
        for (int w = 0; w < 8; w++) p += sblk[w][threadIdx.x];
        g_part[blockIdx.x * 16 + threadIdx.x] = p;
    }
    __threadfence();
    __syncthreads();
    __shared__ bool isLast;
    if (threadIdx.x == 0)
        isLast = (atomicAdd(&g_exit, 1) == GRID - 1);
    __syncthreads();
    if (isLast) {
        __threadfence();
        int f = threadIdx.x & 15, g = threadIdx.x >> 4;
        float s = 0.f;
#pragma unroll 8
        for (int b = g; b < GRID; b += 16) s += g_part[b * 16 + f];
        __shared__ float red2[256];
        red2[threadIdx.x] = s;
        __syncthreads();
        if (threadIdx.x < 16) {
            float t = 0.f;
#pragma unroll
            for (int gg = 0; gg < 16; gg++) t += red2[gg * 16 + threadIdx.x];
            out[threadIdx.x] = t;
        }
        if (threadIdx.x == 0) {      // reset ALL sync state for next replay
            g_barf[0] = 0; g_barf[1] = 0; g_barf[2] = 0;
            g_exit = 0;
            __threadfence();
        }
    }
}

// ---------------- launch ----------------------------------------------------
extern "C" void kernel_launch(void* const* d_in, const int* in_sizes, int n_in,
                              void* d_out, int out_size) {
    const float* x   = (const float*)d_in[0];
    const float* adj = (const float*)d_in[1];
    const float* W0  = (const float*)d_in[2];
    const float* a0s = (const float*)d_in[3];
    const float* a0d = (const float*)d_in[4];
    const float* W1  = (const float*)d_in[5];
    const float* a1s = (const float*)d_in[6];
    const float* a1d = (const float*)d_in[7];
    const float* W2  = (const float*)d_in[8];
    const float* a2s = (const float*)d_in[9];
    const float* a2d = (const float*)d_in[10];
    float* out = (float*)d_out;

    k_gat<<<GRID, 256>>>(x, adj, W0, a0s, a0d, W1, a1s, a1d, W2, a2s, a2d, out);
}

// round 17
// speedup vs baseline: 1.1866x; 1.1866x over previous
#include <cuda_runtime.h>
#include <cstdint>

#define NN     6144
#define MAXDEG 192
#define FULL   0xffffffffu
#define GRID   768

// ---------------- scratch (device globals; no allocation allowed) -----------
__device__ __align__(16) float g_h0[NN * 16];
__device__ __align__(16) float g_h1[NN * 12];
__device__ __align__(16) float g_h2[NN * 20];
__device__ float g_part[GRID * 16];
__device__ int   g_barc[3];            // zero-initialized
__device__ int   g_barf[3];            // zero-initialized
__device__ int   g_exit;               // zero-initialized

#define XOR_RED(v) { _Pragma("unroll") for (int _o = 16; _o > 0; _o >>= 1) (v) += __shfl_xor_sync(FULL, (v), _o); }

__device__ __forceinline__ void grid_barrier(int id) {
    __syncthreads();
    if (threadIdx.x == 0) {
        __threadfence();
        if (atomicAdd(&g_barc[id], 1) == GRID - 1) {
            g_barc[id] = 0;
            asm volatile("st.global.release.gpu.b32 [%0], %1;"
                         :: "l"(&g_barf[id]), "r"(1) : "memory");
        } else {
            int v;
            do {
                asm volatile("ld.global.acquire.gpu.b32 %0, [%1];"
                             : "=r"(v) : "l"(&g_barf[id]) : "memory");
            } while (v == 0);
        }
    }
    __syncthreads();
}

// ======================= single fused persistent kernel ======================
__global__ void __launch_bounds__(256, 6) k_gat(
    const float* __restrict__ x,   const float* __restrict__ adj,
    const float* __restrict__ W0,  const float* __restrict__ a0s, const float* __restrict__ a0d,
    const float* __restrict__ W1,  const float* __restrict__ a1s, const float* __restrict__ a1d,
    const float* __restrict__ W2,  const float* __restrict__ a2s, const float* __restrict__ a2d,
    float* __restrict__ out)
{
    __shared__ float sW0[768];
    __shared__ float sa0[24];
    __shared__ float sW1[72];
    __shared__ float sa1[12];
    __shared__ float sW2[96];
    __shared__ float sa2[32];
    __shared__ int   scols[8][MAXDEG];
    __shared__ float shx[8][16];
    __shared__ float shh[8][16];
    __shared__ float sblk[8][16];

    // ---- load all weights once ----
    for (int i = threadIdx.x; i < 768; i += 256) sW0[i] = W0[i];
    {
        int t = threadIdx.x;
        if (t < 12)  { sa0[t] = a0s[t]; sa0[12 + t] = a0d[t]; }
        if (t >= 32  && t < 104) sW1[t - 32]  = W1[t - 32];
        if (t >= 104 && t < 110) sa1[t - 104] = a1s[t - 104];
        if (t >= 110 && t < 116) sa1[6 + t - 110] = a1d[t - 110];
        if (t >= 128 && t < 224) sW2[t - 128] = W2[t - 128];
        if (t >= 224 && t < 240) sa2[t - 224] = a2d[t - 224];
        if (t >= 240 && t < 256) sa2[16 + t - 240] = a2s[t - 240];
    }
    __syncthreads();

    const int lane = threadIdx.x & 31;
    const int wid  = threadIdx.x >> 5;
    const int node = blockIdx.x * 8 + wid;

    // ============ PHASE 0a: linear0 for own node (es kept in registers) =====
    float es0_0 = 0.f, es1_0 = 0.f;
    {
        float x0 = x[node * 64 + lane];
        float x1 = x[node * 64 + 32 + lane];
        float acc[12];
#pragma unroll
        for (int h = 0; h < 2; h++)
#pragma unroll
            for (int f = 0; f < 6; f++) {
                int hf = h * 6 + f;
                acc[hf] = x0 * sW0[(h * 64 + lane) * 6 + f]
                        + x1 * sW0[(h * 64 + lane + 32) * 6 + f];
            }
#pragma unroll
        for (int i = 0; i < 12; i++) XOR_RED(acc[i]);

        if (lane == 0) {
            float ed0 = 0.f, ed1 = 0.f;
#pragma unroll
            for (int f = 0; f < 6; f++) {
                es0_0 += acc[f]     * sa0[f];       ed0 += acc[f]     * sa0[12 + f];
                es1_0 += acc[6 + f] * sa0[6 + f];   ed1 += acc[6 + f] * sa0[18 + f];
            }
            float4* row = reinterpret_cast<float4*>(&g_h0[node * 16]);
            row[0] = make_float4(acc[0], acc[1], acc[2],  acc[3]);
            row[1] = make_float4(acc[4], acc[5], acc[6],  acc[7]);
            row[2] = make_float4(acc[8], acc[9], acc[10], acc[11]);
            row[3] = make_float4(ed0, ed1, es0_0, es1_0);
        }
        es0_0 = __shfl_sync(FULL, es0_0, 0);
        es1_0 = __shfl_sync(FULL, es1_0, 0);
    }

    grid_barrier(0);   // after this, ALL h0 rows are visible -> gather-on-discover is legal

    // ====== PHASE 0b + PHASE 1 fused: scan own row, gather h0 inline ========
    // Phase-1 state (feature-parallel: j = neighbor slot 0..7, fl = float4 slot)
    const int j  = lane >> 2;
    const int fl = lane & 3;
    const int f0 = fl * 4;
    float4 p1a = {0.f, 0.f, 0.f, 0.f};
    float p1w0 = 0.f, p1w1 = 0.f;

    // one phase-1 gather iteration over scols[k0 .. min(k0+8, limit))
    auto gather8 = [&](int k0, int limit) {
        int k = k0 + j;
        bool valid = k < limit;
        int m = scols[wid][valid ? k : limit - 1];
        float4 hv = *reinterpret_cast<const float4*>(&g_h0[m * 16 + f0]);
        float ed0 = __shfl_sync(FULL, hv.x, 3, 4);
        float ed1 = __shfl_sync(FULL, hv.y, 3, 4);
        float e0 = es0_0 + ed0; e0 = e0 > 0.f ? e0 : 0.2f * e0;
        float e1 = es1_0 + ed1; e1 = e1 > 0.f ? e1 : 0.2f * e1;
        float w0 = __expf(e0), w1 = __expf(e1);
        if (valid) {
            p1w0 += w0; p1w1 += w1;
            float wx = f0     < 6 ? w0 : (f0     < 12 ? w1 : 0.f);
            float wy = f0 + 1 < 6 ? w0 : (f0 + 1 < 12 ? w1 : 0.f);
            float wz = f0 + 2 < 6 ? w0 : (f0 + 2 < 12 ? w1 : 0.f);
            float ww = f0 + 3 < 6 ? w0 : (f0 + 3 < 12 ? w1 : 0.f);
            p1a.x += wx * hv.x; p1a.y += wy * hv.y;
            p1a.z += wz * hv.z; p1a.w += ww * hv.w;
        }
    };

    int deg;
    {
        const uint4* a4 = reinterpret_cast<const uint4*>(adj + (size_t)node * NN);
        int base = 0, done = 0;
        const unsigned lt = (1u << lane) - 1u;
        uint4 va = __ldg(&a4[lane]);
        uint4 vb = __ldg(&a4[32 + lane]);
        for (int c0 = 0; c0 < NN; c0 += 256) {
            uint4 na = {0,0,0,0}, nb = {0,0,0,0};
            if (c0 + 256 < NN) {
                na = __ldg(&a4[((c0 + 256) >> 2) + lane]);
                nb = __ldg(&a4[((c0 + 256) >> 2) + 32 + lane]);
            }
#pragma unroll
            for (int s = 0; s < 2; s++) {
                uint4 v = s == 0 ? va : vb;
                unsigned anyv = v.x | v.y | v.z | v.w;
                unsigned any = __ballot_sync(FULL, anyv != 0);
                if (any) {
                    int col0 = c0 + s * 128 + lane * 4;
                    unsigned m0 = __ballot_sync(FULL, v.x != 0);
                    unsigned m1 = __ballot_sync(FULL, v.y != 0);
                    unsigned m2 = __ballot_sync(FULL, v.z != 0);
                    unsigned m3 = __ballot_sync(FULL, v.w != 0);
                    int c0n = __popc(m0), c1n = __popc(m1), c2n = __popc(m2);
                    if (v.x) { int p = base + __popc(m0 & lt);                   if (p < MAXDEG) scols[wid][p] = col0; }
                    if (v.y) { int p = base + c0n + __popc(m1 & lt);             if (p < MAXDEG) scols[wid][p] = col0 + 1; }
                    if (v.z) { int p = base + c0n + c1n + __popc(m2 & lt);       if (p < MAXDEG) scols[wid][p] = col0 + 2; }
                    if (v.w) { int p = base + c0n + c1n + c2n + __popc(m3 & lt); if (p < MAXDEG) scols[wid][p] = col0 + 3; }
                    base += c0n + c1n + c2n + __popc(m3);
                }
            }
            va = na; vb = nb;
            // drain complete groups of 8 discovered neighbors (gathers overlap stream)
            int bcap = base < MAXDEG ? base : MAXDEG;
            if (done + 8 <= bcap) {
                __syncwarp();   // scols written by other lanes
                do { gather8(done, done + 8); done += 8; } while (done + 8 <= bcap);
            }
        }
        deg = base < MAXDEG ? base : MAXDEG;
        // tail: remaining partial group
        if (done < deg) {
            __syncwarp();
            gather8(done, deg);
        }
    }

    // ---- phase-1 epilogue: merge, softmax-normalize, elu, linear1 ----------
    float es0_1 = 0.f, es1_1 = 0.f;
    {
#pragma unroll
        for (int o = 4; o <= 16; o <<= 1) {
            p1a.x += __shfl_xor_sync(FULL, p1a.x, o);
            p1a.y += __shfl_xor_sync(FULL, p1a.y, o);
            p1a.z += __shfl_xor_sync(FULL, p1a.z, o);
            p1a.w += __shfl_xor_sync(FULL, p1a.w, o);
            p1w0  += __shfl_xor_sync(FULL, p1w0, o);
            p1w1  += __shfl_xor_sync(FULL, p1w1, o);
        }
        if (lane < 3) {
            float inv0 = 1.f / p1w0, inv1 = 1.f / p1w1;
            float v0 = p1a.x * (f0     < 6 ? inv0 : inv1);
            float v1 = p1a.y * (f0 + 1 < 6 ? inv0 : inv1);
            float v2 = p1a.z * (f0 + 2 < 6 ? inv0 : inv1);
            float v3 = p1a.w * (f0 + 3 < 6 ? inv0 : inv1);
            shx[wid][f0]     = v0 > 0.f ? v0 : expm1f(v0);
            shx[wid][f0 + 1] = v1 > 0.f ? v1 : expm1f(v1);
            shx[wid][f0 + 2] = v2 > 0.f ? v2 : expm1f(v2);
            shx[wid][f0 + 3] = v3 > 0.f ? v3 : expm1f(v3);
        }
        __syncwarp();
        if (lane < 6) {
            int h2 = lane / 3, f2 = lane % 3;
            float s = 0.f;
#pragma unroll
            for (int i = 0; i < 12; i++) s += shx[wid][i] * sW1[(h2 * 12 + i) * 3 + f2];
            g_h1[node * 12 + lane] = s;
            shh[wid][lane] = s;
        }
        __syncwarp();
        float es_l = 0.f;
        if (lane < 2) {
            float ed = 0.f;
#pragma unroll
            for (int f2 = 0; f2 < 3; f2++) {
                float hv = shh[wid][lane * 3 + f2];
                es_l += hv * sa1[lane * 3 + f2];
                ed   += hv * sa1[6 + lane * 3 + f2];
            }
            g_h1[node * 12 + 6 + lane] = ed;
        }
        es0_1 = __shfl_sync(FULL, es_l, 0);
        es1_1 = __shfl_sync(FULL, es_l, 1);
    }

    grid_barrier(1);

    // ============ PHASE 2: attn layer1 (H=2,F=3) + elu + linear2 ============
    float es_2 = 0.f;
    {
        const int j2  = lane >> 1;
        const int fl2 = lane & 1;

        float4 a = {0.f, 0.f, 0.f, 0.f};
        float ws0 = 0.f, ws1 = 0.f;
#pragma unroll 2
        for (int kb = 0; kb < deg; kb += 16) {
            int k = kb + j2;
            bool valid = k < deg;
            int m = scols[wid][valid ? k : deg - 1];
            float4 hv = *reinterpret_cast<const float4*>(&g_h1[m * 12 + fl2 * 4]);
            float ed0 = __shfl_sync(FULL, hv.z, 1, 2);
            float ed1 = __shfl_sync(FULL, hv.w, 1, 2);
            float e0 = es0_1 + ed0; e0 = e0 > 0.f ? e0 : 0.2f * e0;
            float e1 = es1_1 + ed1; e1 = e1 > 0.f ? e1 : 0.2f * e1;
            float w0 = __expf(e0), w1 = __expf(e1);
            if (valid) {
                ws0 += w0; ws1 += w1;
                if (fl2 == 0) {
                    a.x += w0 * hv.x; a.y += w0 * hv.y;
                    a.z += w0 * hv.z; a.w += w1 * hv.w;
                } else {
                    a.x += w1 * hv.x; a.y += w1 * hv.y;
                }
            }
        }
#pragma unroll
        for (int o = 2; o <= 16; o <<= 1) {
            a.x += __shfl_xor_sync(FULL, a.x, o);
            a.y += __shfl_xor_sync(FULL, a.y, o);
            a.z += __shfl_xor_sync(FULL, a.z, o);
            a.w += __shfl_xor_sync(FULL, a.w, o);
            ws0 += __shfl_xor_sync(FULL, ws0, o);
            ws1 += __shfl_xor_sync(FULL, ws1, o);
        }

        if (lane < 2) {
            float inv0 = 1.f / ws0, inv1 = 1.f / ws1;
            if (lane == 0) {
                float v0 = a.x * inv0, v1 = a.y * inv0, v2 = a.z * inv0, v3 = a.w * inv1;
                shx[wid][0] = v0 > 0.f ? v0 : expm1f(v0);
                shx[wid][1] = v1 > 0.f ? v1 : expm1f(v1);
                shx[wid][2] = v2 > 0.f ? v2 : expm1f(v2);
                shx[wid][3] = v3 > 0.f ? v3 : expm1f(v3);
            } else {
                float v4 = a.x * inv1, v5 = a.y * inv1;
                shx[wid][4] = v4 > 0.f ? v4 : expm1f(v4);
                shx[wid][5] = v5 > 0.f ? v5 : expm1f(v5);
            }
        }
        __syncwarp();
        if (lane < 16) {
            float s = 0.f;
#pragma unroll
            for (int i = 0; i < 6; i++) s += shx[wid][i] * sW2[i * 16 + lane];
            g_h2[node * 20 + lane] = s;
            shh[wid][lane] = s;
        }
        __syncwarp();
        float d_l = 0.f;
        if (lane < 2) {
#pragma unroll
            for (int f = 0; f < 16; f++) d_l += shh[wid][f] * sa2[lane * 16 + f];
            if (lane == 0) g_h2[node * 20 + 16] = d_l;
        }
        es_2 = __shfl_sync(FULL, d_l, 1);
    }

    grid_barrier(2);

    // ===== PHASE 3: final attn (H=1,F=16) + relu + deterministic sum ========
    {
        float4 a = {0.f, 0.f, 0.f, 0.f};
        float ws = 0.f;
#pragma unroll 4
        for (int kb = 0; kb < deg; kb += 8) {
            int k = kb + j;
            bool valid = k < deg;
            int m = scols[wid][valid ? k : deg - 1];
            float4 hv = *reinterpret_cast<const float4*>(&g_h2[m * 20 + fl * 4]);
            float ed = g_h2[m * 20 + 16];
            float e = es_2 + ed; e = e > 0.f ? e : 0.2f * e;
            float w = __expf(e);
            if (valid) {
                ws += w;
                a.x += w * hv.x; a.y += w * hv.y;
                a.z += w * hv.z; a.w += w * hv.w;
            }
        }
#pragma unroll
        for (int o = 4; o <= 16; o <<= 1) {
            a.x += __shfl_xor_sync(FULL, a.x, o);
            a.y += __shfl_xor_sync(FULL, a.y, o);
            a.z += __shfl_xor_sync(FULL, a.z, o);
            a.w += __shfl_xor_sync(FULL, a.w, o);
            ws  += __shfl_xor_sync(FULL, ws, o);
        }

        if (lane < 4) {
            float inv = 1.f / ws;
            float v0 = a.x * inv, v1 = a.y * inv, v2 = a.z * inv, v3 = a.w * inv;
            sblk[wid][fl * 4]     = v0 > 0.f ? v0 : 0.f;
            sblk[wid][fl * 4 + 1] = v1 > 0.f ? v1 : 0.f;
            sblk[wid][fl * 4 + 2] = v2 > 0.f ? v2 : 0.f;
            sblk[wid][fl * 4 + 3] = v3 > 0.f ? v3 : 0.f;
        }
    }
    __syncthreads();

    if (threadIdx.x < 16) {
        float p = 0.f;
#pragma unroll
        for (int w = 0; w < 8; w++) p += sblk[w][threadIdx.x];
        g_part[blockIdx.x * 16 + threadIdx.x] = p;
    }
    __threadfence();
    __syncthreads();
    __shared__ bool isLast;
    if (threadIdx.x == 0)
        isLast = (atomicAdd(&g_exit, 1) == GRID - 1);
    __syncthreads();
    if (isLast) {
        __threadfence();
        int f = threadIdx.x & 15, g = threadIdx.x >> 4;
        float s = 0.f;
#pragma unroll 8
        for (int b = g; b < GRID; b += 16) s += g_part[b * 16 + f];
        __shared__ float red2[256];
        red2[threadIdx.x] = s;
        __syncthreads();
        if (threadIdx.x < 16) {
            float t = 0.f;
#pragma unroll
            for (int gg = 0; gg < 16; gg++) t += red2[gg * 16 + threadIdx.x];
            out[threadIdx.x] = t;
        }
        if (threadIdx.x == 0) {      // reset ALL sync state for next replay
            g_barf[0] = 0; g_barf[1] = 0; g_barf[2] = 0;
            g_exit = 0;
            __threadfence();
        }
    }
}

// ---------------- launch ----------------------------------------------------
extern "C" void kernel_launch(void* const* d_in, const int* in_sizes, int n_in,
                              void* d_out, int out_size) {
    const float* x   = (const float*)d_in[0];
    const float* adj = (const float*)d_in[1];
    const float* W0  = (const float*)d_in[2];
    const float* a0s = (const float*)d_in[3];
    const float* a0d = (const float*)d_in[4];
    const float* W1  = (const float*)d_in[5];
    const float* a1s = (const float*)d_in[6];
    const float* a1d = (const float*)d_in[7];
    const float* W2  = (const float*)d_in[8];
    const float* a2s = (const float*)d_in[9];
    const float* a2d = (const float*)d_in[10];
    float* out = (float*)d_out;

    k_gat<<<GRID, 256>>>(x, adj, W0, a0s, a0d, W1, a1s, a1d, W2, a2s, a2d, out);
}